// round 16
// baseline (speedup 1.0000x reference)
#include <cuda_runtime.h>
#include <cstdint>

// TripletCenterLoss — single fused kernel. mma.sync tf32, 3-stage cp.async.
// B=8192, D=512, NC=55, margin=0.2. targets int32.
// R14: CTA = 128 thr = 4 K-quarter warps, MTILE=16, grid 512, 6 CTAs/SM.

#define BB 8192
#define DD 512
#define NC 55
#define MARGINF 0.2f

#define MTILE 16
#define GRID_MAIN (BB / MTILE)   // 512
#define CHK 32                   // K-floats per chunk
#define NCH (DD / CHK)           // 16
#define NSTG 3                   // pipeline stages
#define PADF 36                  // floats per smem row (conflict-free, 16B mult)
#define AROWS 16
#define BROWS 56
#define STGF ((AROWS + BROWS) * PADF)   // 2592 floats per stage

__device__ float2 g_partial[GRID_MAIN];
__device__ int    g_done = 0;

__device__ __forceinline__ uint32_t smem_u32(const void* p) {
    uint32_t a;
    asm("{ .reg .u64 t; cvta.to.shared.u64 t, %1; cvt.u32.u64 %0, t; }"
        : "=r"(a) : "l"(p));
    return a;
}
__device__ __forceinline__ void cpa16(uint32_t dst, const void* src) {
    asm volatile("cp.async.cg.shared.global [%0], [%1], 16;"
                 :: "r"(dst), "l"(src));
}
#define CP_COMMIT() asm volatile("cp.async.commit_group;" ::: "memory")
#define CP_WAIT(n)  asm volatile("cp.async.wait_group %0;" :: "n"(n) : "memory")

__device__ __forceinline__ uint32_t f2tf(float f) {
    uint32_t r;
    asm("cvt.rna.tf32.f32 %0, %1;" : "=r"(r) : "f"(f));
    return r;
}
__device__ __forceinline__ void mma_tf32(float* d, uint32_t a0, uint32_t a1,
                                         uint32_t a2, uint32_t a3,
                                         uint32_t b0, uint32_t b1) {
    asm volatile(
        "mma.sync.aligned.m16n8k8.row.col.f32.tf32.tf32.f32 "
        "{%0,%1,%2,%3}, {%4,%5,%6,%7}, {%8,%9}, {%0,%1,%2,%3};"
        : "+f"(d[0]), "+f"(d[1]), "+f"(d[2]), "+f"(d[3])
        : "r"(a0), "r"(a1), "r"(a2), "r"(a3), "r"(b0), "r"(b1));
}

// ============================================================
// Fused kernel: grid 512 x 128 threads
// ============================================================
__global__ __launch_bounds__(128, 6)
void tcl_mma_kernel(const float* __restrict__ x,
                    const int* __restrict__ tgt,
                    const float* __restrict__ cen,
                    float* __restrict__ out) {
    __shared__ __align__(16) float pool[NSTG * STGF];   // 31104 B
    __shared__ float  xn[MTILE];
    __shared__ float  scn[56];       // exact center norms
    __shared__ int    sflags[56];    // class-present flags
    __shared__ float2 red1;
    __shared__ int    lastflag;

    const int tid  = threadIdx.x;
    const int kq   = tid >> 5;       // warp = K-quarter (0..3)
    const int lane = tid & 31;
    const int g    = lane >> 2;      // fragment group row
    const int q4   = lane & 3;       // fragment group col
    const int r0   = blockIdx.x * MTILE;

    const uint32_t pool_sa = smem_u32(pool);

    // ---- staging maps (float4 slots, per chunk) ----
    // A: 128 slots: row = tid>>3 (0..15), sl = tid&7
    const int arow = tid >> 3, asl = tid & 7;
    const float4* __restrict__ xg =
        (const float4*)(x + (size_t)(r0 + arow) * DD) + asl;
    const uint32_t adst = (uint32_t)((arow * PADF + asl * 4) * 4);
    // B: 440 valid slots (55 rows x 8): idx = tid + q*128
    const float4* __restrict__ bgp[4];
    uint32_t bdst[4];
    int bok[4], browq[4];
    #pragma unroll
    for (int q = 0; q < 4; q++) {
        int idx = tid + q * 128;
        int brow = idx >> 3, bsl = idx & 7;
        bok[q]   = (idx < 440);
        browq[q] = brow;
        int lr = brow < NC ? brow : NC - 1;
        bgp[q]  = (const float4*)(cen + (size_t)lr * DD) + bsl;
        bdst[q] = (uint32_t)(((AROWS + brow) * PADF + bsl * 4) * 4);
    }

    // zero B pad row (row 55) in all stages — never overwritten afterwards
    if (tid < NSTG * 8) {
        int st = tid >> 3, sl = tid & 7;
        *(float4*)(pool + st * STGF + (AROWS + 55) * PADF + sl * 4) =
            make_float4(0.f, 0.f, 0.f, 0.f);
    }

    // ---- prologue: issue chunks 0, 1 ----
    #pragma unroll
    for (int c = 0; c < NSTG - 1; c++) {
        const uint32_t bb = pool_sa + (uint32_t)(c * STGF * 4);
        cpa16(bb + adst, xg + c * 8);
        #pragma unroll
        for (int q = 0; q < 4; q++)
            if (bok[q]) cpa16(bb + bdst[q], bgp[q] + c * 8);
        CP_COMMIT();
    }

    // ---- present flags: full tgt scan (overlaps the cp.async prologue) ----
    if (tid < 56) sflags[tid] = 0;
    __syncthreads();
    {
        const int4* tg4 = (const int4*)tgt;
        #pragma unroll
        for (int q = 0; q < 16; q++) {
            int4 v = __ldg(tg4 + tid + q * 128);
            sflags[v.x] = 1; sflags[v.y] = 1;
            sflags[v.z] = 1; sflags[v.w] = 1;
        }
    }

    // ---- accumulators ----
    float d[7][4];
    #pragma unroll
    for (int j = 0; j < 7; j++)
        d[j][0] = d[j][1] = d[j][2] = d[j][3] = 0.0f;
    float na = 0.0f;
    float nb[4] = {0.f, 0.f, 0.f, 0.f};

    int buf = 0;
    #pragma unroll 1
    for (int c = 0; c < NCH; c++) {
        CP_WAIT(NSTG - 2);       // chunk c landed
        __syncthreads();         // all warps done with buf (c-1)%NSTG

        // issue chunk c+2 into buf (c+2)%NSTG (freed by the bar above)
        if (c + NSTG - 1 < NCH) {
            int nbuf = buf + (NSTG - 1);
            if (nbuf >= NSTG) nbuf -= NSTG;
            const uint32_t bb = pool_sa + (uint32_t)(nbuf * STGF * 4);
            const int ofs = (c + NSTG - 1) * 8;
            cpa16(bb + adst, xg + ofs);
            #pragma unroll
            for (int q = 0; q < 4; q++)
                if (bok[q]) cpa16(bb + bdst[q], bgp[q] + ofs);
        }
        CP_COMMIT();             // empty groups at tail keep the count aligned

        const float* As = pool + buf * STGF;
        const float* Bs = As + AROWS * PADF;

        // exact norm accumulation from raw staged data
        {
            float4 v = *(const float4*)(As + arow * PADF + asl * 4);
            na += v.x * v.x + v.y * v.y + v.z * v.z + v.w * v.w;
            #pragma unroll
            for (int q = 0; q < 4; q++) {
                if (!bok[q]) continue;
                float4 b = *(const float4*)((const float*)pool + buf * STGF
                                            + (bdst[q] >> 2));
                nb[q] += b.x * b.x + b.y * b.y + b.z * b.z + b.w * b.w;
            }
        }

        // my K-quarter: 1 k8-step of this chunk (rna in registers)
        {
            const int k0 = kq * 8 + q4;
            const uint32_t* aF0 = (const uint32_t*)(As + g * PADF);
            const uint32_t* aF1 = aF0 + 8 * PADF;
            uint32_t a0 = f2tf(__uint_as_float(aF0[k0]));
            uint32_t a1 = f2tf(__uint_as_float(aF1[k0]));
            uint32_t a2 = f2tf(__uint_as_float(aF0[k0 + 4]));
            uint32_t a3 = f2tf(__uint_as_float(aF1[k0 + 4]));
            #pragma unroll
            for (int j = 0; j < 7; j++) {
                const uint32_t* bb2 = (const uint32_t*)(Bs + (j * 8 + g) * PADF);
                uint32_t b0 = f2tf(__uint_as_float(bb2[k0]));
                uint32_t b1 = f2tf(__uint_as_float(bb2[k0 + 4]));
                mma_tf32(d[j], a0, a1, a2, a3, b0, b1);
            }
        }

        if (++buf == NSTG) buf = 0;
    }

    // ---- A row norms: reduce over the 8 staging lanes of each row ----
    #pragma unroll
    for (int o = 1; o < 8; o <<= 1) na += __shfl_xor_sync(0xffffffffu, na, o);
    if ((tid & 7) == 0) xn[arow] = na;

    // ---- B row norms: 8 consecutive lanes share a row ----
    #pragma unroll
    for (int q = 0; q < 4; q++) {
        #pragma unroll
        for (int o = 1; o < 8; o <<= 1)
            nb[q] += __shfl_xor_sync(0xffffffffu, nb[q], o);
        if (bok[q] && (tid & 7) == 0) scn[browq[q]] = nb[q];
    }

    __syncthreads();   // pool free for reuse; xn/scn/sflags complete

    // ---- combine K-quarters (comb aliases the staging pool) ----
    float* comb = pool;                      // needs 2688 floats, pool has 7776
    if (kq > 0) {
        #pragma unroll
        for (int j = 0; j < 7; j++) {
            float4* p = (float4*)(comb + (((kq - 1) * 7 + j) * 128 + lane * 4));
            *p = make_float4(d[j][0], d[j][1], d[j][2], d[j][3]);
        }
    }
    __syncthreads();

    if (kq == 0) {
        #pragma unroll
        for (int r = 0; r < 3; r++) {
            #pragma unroll
            for (int j = 0; j < 7; j++) {
                float4 v = *(const float4*)(comb + ((r * 7 + j) * 128 + lane * 4));
                d[j][0] += v.x; d[j][1] += v.y; d[j][2] += v.z; d[j][3] += v.w;
            }
        }

        // ---- epilogue: rows g and g+8 ----
        float lsum = 0.0f, psum = 0.0f;
        #pragma unroll
        for (int half = 0; half < 2; half++) {
            const int lrow = g + half * 8;
            const float xnv = xn[lrow];
            const int   tg  = tgt[r0 + lrow];
            float ap = -1e30f, an = 1e30f;
            #pragma unroll
            for (int j = 0; j < 7; j++) {
                #pragma unroll
                for (int e = 0; e < 2; e++) {
                    int n = j * 8 + 2 * q4 + e;
                    if (n >= NC || !sflags[n]) continue;
                    float S = d[j][half * 2 + e];
                    float d2 = xnv + scn[n] - 2.0f * S;
                    float dd = sqrtf(fmaxf(d2, 1e-12f));
                    if (n == tg) ap = dd;
                    else an = fminf(an, dd);
                }
            }
            #pragma unroll
            for (int o = 1; o < 4; o <<= 1) {
                ap = fmaxf(ap, __shfl_xor_sync(0xffffffffu, ap, o));
                an = fminf(an, __shfl_xor_sync(0xffffffffu, an, o));
            }
            if (q4 == 0) {
                lsum += fmaxf(ap - an + MARGINF, 0.0f);
                psum += (an > ap) ? 1.0f : 0.0f;
            }
        }
        #pragma unroll
        for (int o = 16; o; o >>= 1) {
            lsum += __shfl_xor_sync(0xffffffffu, lsum, o);
            psum += __shfl_xor_sync(0xffffffffu, psum, o);
        }
        if (lane == 0) red1 = make_float2(lsum, psum);
    }
    __syncthreads();

    // ---- publish partial + last-block finalize ----
    if (tid == 0) {
        g_partial[blockIdx.x] = red1;
        __threadfence();
        int old = atomicAdd(&g_done, 1);
        lastflag = (old == GRID_MAIN - 1) ? 1 : 0;
    }
    __syncthreads();

    if (lastflag) {
        float2* fs = (float2*)pool;          // 128 float2, aliases pool
        float2 acc = make_float2(0.f, 0.f);
        #pragma unroll
        for (int q = 0; q < 4; q++) {
            float2 v = g_partial[tid + q * 128];
            acc.x += v.x; acc.y += v.y;
        }
        fs[tid] = acc;
        __syncthreads();
        #pragma unroll
        for (int o = 64; o; o >>= 1) {
            if (tid < o) { fs[tid].x += fs[tid + o].x; fs[tid].y += fs[tid + o].y; }
            __syncthreads();
        }
        if (tid == 0) {
            out[0] = fs[0].x / (float)BB;
            out[1] = fs[0].y / (float)BB;
            g_done = 0;   // reset for graph replay
        }
    }
}

extern "C" void kernel_launch(void* const* d_in, const int* in_sizes, int n_in,
                              void* d_out, int out_size) {
    const float* x   = (const float*)d_in[0];
    const int*   tgt = (const int*)d_in[1];
    const float* cen = (const float*)d_in[2];
    float* out = (float*)d_out;

    tcl_mma_kernel<<<GRID_MAIN, 128>>>(x, tgt, cen, out);
}

// round 17
// speedup vs baseline: 1.0851x; 1.0851x over previous
#include <cuda_runtime.h>
#include <cstdint>

// TripletCenterLoss — single fused kernel. mma.sync tf32, 3-stage cp.async.
// B=8192, D=512, NC=55, margin=0.2. targets int32.
// R17: CTA = 512 thr = 2 M-halves x 4 K-quarters x 2 N-halves, MTILE=32,
//      grid 256 -> 4096 warps (2x R13 occupancy at constant traffic).

#define BB 8192
#define DD 512
#define NC 55
#define MARGINF 0.2f

#define MTILE 32
#define GRID_MAIN (BB / MTILE)   // 256
#define CHK 32                   // K-floats per chunk
#define NCH (DD / CHK)           // 16
#define NSTG 3                   // pipeline stages
#define PADF 36                  // floats per smem row (conflict-free, 16B mult)
#define AROWS 32
#define BROWS 56
#define STGF ((AROWS + BROWS) * PADF)   // 3168 floats per stage

__device__ float2 g_partial[GRID_MAIN];
__device__ int    g_done = 0;

__device__ __forceinline__ uint32_t smem_u32(const void* p) {
    uint32_t a;
    asm("{ .reg .u64 t; cvta.to.shared.u64 t, %1; cvt.u32.u64 %0, t; }"
        : "=r"(a) : "l"(p));
    return a;
}
__device__ __forceinline__ void cpa16(uint32_t dst, const void* src) {
    asm volatile("cp.async.cg.shared.global [%0], [%1], 16;"
                 :: "r"(dst), "l"(src));
}
#define CP_COMMIT() asm volatile("cp.async.commit_group;" ::: "memory")
#define CP_WAIT(n)  asm volatile("cp.async.wait_group %0;" :: "n"(n) : "memory")

__device__ __forceinline__ uint32_t f2tf(float f) {
    uint32_t r;
    asm("cvt.rna.tf32.f32 %0, %1;" : "=r"(r) : "f"(f));
    return r;
}
__device__ __forceinline__ void mma_tf32(float* d, uint32_t a0, uint32_t a1,
                                         uint32_t a2, uint32_t a3,
                                         uint32_t b0, uint32_t b1) {
    asm volatile(
        "mma.sync.aligned.m16n8k8.row.col.f32.tf32.tf32.f32 "
        "{%0,%1,%2,%3}, {%4,%5,%6,%7}, {%8,%9}, {%0,%1,%2,%3};"
        : "+f"(d[0]), "+f"(d[1]), "+f"(d[2]), "+f"(d[3])
        : "r"(a0), "r"(a1), "r"(a2), "r"(a3), "r"(b0), "r"(b1));
}

// ============================================================
// Fused kernel: grid 256 x 512 threads
// warp w: wm = w&1 (M-half), kq = (w>>1)&3 (K-quarter), nh = w>>3 (N-half)
// ============================================================
__global__ __launch_bounds__(512, 2)
void tcl_mma_kernel(const float* __restrict__ x,
                    const int* __restrict__ tgt,
                    const float* __restrict__ cen,
                    float* __restrict__ out) {
    __shared__ __align__(16) float pool[NSTG * STGF];   // 38016 B
    __shared__ float  xn[MTILE];
    __shared__ float  scn[56];       // exact center norms
    __shared__ int    sflags[56];    // class-present flags
    __shared__ float  sap[2][MTILE]; // per-N-half hardest-positive
    __shared__ float  san[2][MTILE]; // per-N-half hardest-negative
    __shared__ float2 red1;
    __shared__ int    lastflag;

    const int tid  = threadIdx.x;
    const int w    = tid >> 5;
    const int lane = tid & 31;
    const int wm   = w & 1;            // M-half
    const int kq   = (w >> 1) & 3;     // K-quarter
    const int nh   = w >> 3;           // N-half
    const int NJ   = 4 - nh;           // j-blocks: 4 (cols 0..31) or 3 (32..55)
    const int g    = lane >> 2;        // fragment group row
    const int q4   = lane & 3;         // fragment group col
    const int r0   = blockIdx.x * MTILE;

    const uint32_t pool_sa = smem_u32(pool);

    // ---- staging maps (float4 slots, per chunk) ----
    // A: 256 slots: threads tid<256, row = tid>>3 (0..31), sl = tid&7
    const int aok  = tid < 256;
    const int arow = (tid & 255) >> 3, asl = tid & 7;
    const float4* __restrict__ xg =
        (const float4*)(x + (size_t)(r0 + arow) * DD) + asl;
    const uint32_t adst = (uint32_t)((arow * PADF + asl * 4) * 4);
    // B: 440 slots: threads tid<440, row = tid>>3 (0..54), sl = tid&7
    const int bok  = tid < 440;
    const int brow = (tid >> 3) < 55 ? (tid >> 3) : 54;
    const int bsl  = tid & 7;
    const float4* __restrict__ bg =
        (const float4*)(cen + (size_t)brow * DD) + bsl;
    const uint32_t bdst = (uint32_t)(((AROWS + brow) * PADF + bsl * 4) * 4);

    // zero B pad row (row 55) in all stages — never overwritten afterwards
    if (tid < NSTG * 8) {
        int st = tid >> 3, sl = tid & 7;
        *(float4*)(pool + st * STGF + (AROWS + 55) * PADF + sl * 4) =
            make_float4(0.f, 0.f, 0.f, 0.f);
    }

    // ---- prologue: issue chunks 0, 1 ----
    #pragma unroll
    for (int c = 0; c < NSTG - 1; c++) {
        const uint32_t bb = pool_sa + (uint32_t)(c * STGF * 4);
        if (aok) cpa16(bb + adst, xg + c * 8);
        if (bok) cpa16(bb + bdst, bg + c * 8);
        CP_COMMIT();
    }

    // ---- present flags: full tgt scan (overlaps the cp.async prologue) ----
    if (tid < 56) sflags[tid] = 0;
    __syncthreads();
    {
        const int4* tg4 = (const int4*)tgt;
        #pragma unroll
        for (int q = 0; q < 4; q++) {
            int4 v = __ldg(tg4 + tid + q * 512);
            sflags[v.x] = 1; sflags[v.y] = 1;
            sflags[v.z] = 1; sflags[v.w] = 1;
        }
    }

    // ---- accumulators ----
    float d[4][4];
    #pragma unroll
    for (int j = 0; j < 4; j++)
        d[j][0] = d[j][1] = d[j][2] = d[j][3] = 0.0f;
    float na = 0.0f, nb = 0.0f;

    int buf = 0;
    #pragma unroll 1
    for (int c = 0; c < NCH; c++) {
        CP_WAIT(NSTG - 2);       // chunk c landed
        __syncthreads();         // all warps done with buf (c-1)%NSTG

        // issue chunk c+2 into buf (c+2)%NSTG (freed by the bar above)
        if (c + NSTG - 1 < NCH) {
            int nbuf = buf + (NSTG - 1);
            if (nbuf >= NSTG) nbuf -= NSTG;
            const uint32_t bb = pool_sa + (uint32_t)(nbuf * STGF * 4);
            const int ofs = (c + NSTG - 1) * 8;
            if (aok) cpa16(bb + adst, xg + ofs);
            if (bok) cpa16(bb + bdst, bg + ofs);
        }
        CP_COMMIT();             // empty groups at tail keep the count aligned

        const float* As = pool + buf * STGF;
        const float* Bs = As + AROWS * PADF;

        // exact norm accumulation from raw staged data
        if (aok) {
            float4 v = *(const float4*)(As + arow * PADF + asl * 4);
            na += v.x * v.x + v.y * v.y + v.z * v.z + v.w * v.w;
        }
        if (bok) {
            float4 b = *(const float4*)((const float*)pool + buf * STGF
                                        + (bdst >> 2));
            nb += b.x * b.x + b.y * b.y + b.z * b.z + b.w * b.w;
        }

        // my (K-quarter, N-half): 1 k8-step, NJ j-blocks
        {
            const int k0 = kq * 8 + q4;
            const uint32_t* aF0 = (const uint32_t*)(As + (wm * 16 + g) * PADF);
            const uint32_t* aF1 = aF0 + 8 * PADF;
            uint32_t a0 = f2tf(__uint_as_float(aF0[k0]));
            uint32_t a1 = f2tf(__uint_as_float(aF1[k0]));
            uint32_t a2 = f2tf(__uint_as_float(aF0[k0 + 4]));
            uint32_t a3 = f2tf(__uint_as_float(aF1[k0 + 4]));
            #pragma unroll
            for (int j = 0; j < 4; j++) {
                if (j >= NJ) break;
                const uint32_t* bb2 =
                    (const uint32_t*)(Bs + ((nh * 32 + j * 8) + g) * PADF);
                uint32_t b0 = f2tf(__uint_as_float(bb2[k0]));
                uint32_t b1 = f2tf(__uint_as_float(bb2[k0 + 4]));
                mma_tf32(d[j], a0, a1, a2, a3, b0, b1);
            }
        }

        if (++buf == NSTG) buf = 0;
    }

    // ---- norms: 8 consecutive lanes share a row ----
    #pragma unroll
    for (int o = 1; o < 8; o <<= 1) {
        na += __shfl_xor_sync(0xffffffffu, na, o);
        nb += __shfl_xor_sync(0xffffffffu, nb, o);
    }
    if (aok && (tid & 7) == 0) xn[arow] = na;
    if (bok && (tid & 7) == 0) scn[brow] = nb;

    __syncthreads();   // pool free for reuse; xn/scn/sflags complete

    // ---- combine K-quarters (comb aliases the staging pool) ----
    // slot = (nh*2+wm)*3 + (kq-1), 12 slots x 512 floats = 6144 <= 9504
    float* comb = pool;
    if (kq > 0) {
        const int slot = (nh * 2 + wm) * 3 + (kq - 1);
        #pragma unroll
        for (int j = 0; j < 4; j++) {
            float4* p = (float4*)(comb + (slot * 4 + j) * 128 + lane * 4);
            *p = make_float4(d[j][0], d[j][1], d[j][2], d[j][3]);
        }
    }
    __syncthreads();

    if (kq == 0) {
        #pragma unroll
        for (int r = 0; r < 3; r++) {
            const int slot = (nh * 2 + wm) * 3 + r;
            #pragma unroll
            for (int j = 0; j < 4; j++) {
                float4 v = *(const float4*)(comb + (slot * 4 + j) * 128
                                            + lane * 4);
                d[j][0] += v.x; d[j][1] += v.y; d[j][2] += v.z; d[j][3] += v.w;
            }
        }

        // ---- per-half epilogue: rows wm*16+g and +8, classes of this half ----
        #pragma unroll
        for (int half = 0; half < 2; half++) {
            const int lrow = wm * 16 + g + half * 8;
            const float xnv = xn[lrow];
            const int   tg  = tgt[r0 + lrow];
            float ap = -1e30f, an = 1e30f;
            #pragma unroll
            for (int j = 0; j < 4; j++) {
                if (j >= NJ) break;
                #pragma unroll
                for (int e = 0; e < 2; e++) {
                    int n = nh * 32 + j * 8 + 2 * q4 + e;
                    if (n >= NC || !sflags[n]) continue;
                    float S = d[j][half * 2 + e];
                    float d2 = xnv + scn[n] - 2.0f * S;
                    float dd = sqrtf(fmaxf(d2, 1e-12f));
                    if (n == tg) ap = dd;
                    else an = fminf(an, dd);
                }
            }
            #pragma unroll
            for (int o = 1; o < 4; o <<= 1) {
                ap = fmaxf(ap, __shfl_xor_sync(0xffffffffu, ap, o));
                an = fminf(an, __shfl_xor_sync(0xffffffffu, an, o));
            }
            if (q4 == 0) {
                sap[nh][lrow] = ap;
                san[nh][lrow] = an;
            }
        }
    }
    __syncthreads();

    // ---- merge N-halves + block loss (warp 0, one row per lane) ----
    if (w == 0) {
        const float ap = fmaxf(sap[0][lane], sap[1][lane]);
        const float an = fminf(san[0][lane], san[1][lane]);
        float lsum = fmaxf(ap - an + MARGINF, 0.0f);
        float psum = (an > ap) ? 1.0f : 0.0f;
        #pragma unroll
        for (int o = 16; o; o >>= 1) {
            lsum += __shfl_xor_sync(0xffffffffu, lsum, o);
            psum += __shfl_xor_sync(0xffffffffu, psum, o);
        }
        if (lane == 0) red1 = make_float2(lsum, psum);
    }
    __syncthreads();

    // ---- publish partial + last-block finalize ----
    if (tid == 0) {
        g_partial[blockIdx.x] = red1;
        __threadfence();
        int old = atomicAdd(&g_done, 1);
        lastflag = (old == GRID_MAIN - 1) ? 1 : 0;
    }
    __syncthreads();

    if (lastflag) {
        float2* fs = (float2*)pool;          // 256 float2, aliases pool
        if (tid < 256) fs[tid] = g_partial[tid];
        __syncthreads();
        #pragma unroll
        for (int o = 128; o; o >>= 1) {
            if (tid < o) { fs[tid].x += fs[tid + o].x; fs[tid].y += fs[tid + o].y; }
            __syncthreads();
        }
        if (tid == 0) {
            out[0] = fs[0].x / (float)BB;
            out[1] = fs[0].y / (float)BB;
            g_done = 0;   // reset for graph replay
        }
    }
}

extern "C" void kernel_launch(void* const* d_in, const int* in_sizes, int n_in,
                              void* d_out, int out_size) {
    const float* x   = (const float*)d_in[0];
    const int*   tgt = (const int*)d_in[1];
    const float* cen = (const float*)d_in[2];
    float* out = (float*)d_out;

    tcl_mma_kernel<<<GRID_MAIN, 512>>>(x, tgt, cen, out);
}